// round 11
// baseline (speedup 1.0000x reference)
#include <cuda_runtime.h>
#include <cuda_bf16.h>
#include <math.h>
#include <stdint.h>

#define NSEQ 2048
#define NB 2
#define NH 16
#define DH 64
#define DIM 1024

// Scratch (static __device__ — no cudaMalloc allowed)
__device__ __align__(16) float g_q[NB * NH * NSEQ * DH];
__device__ __align__(16) float g_k[NB * NH * NSEQ * DH];
__device__ __align__(16) float g_v[NB * NH * NSEQ * DH];
__device__ __align__(16) float g_ao[NB * NSEQ * DIM];
__device__ __align__(16) float g_bias[NH * 4096];

// ---------------------------------------------------------------------------
// mma.sync m16n8k16 bf16 + inline hi/lo split helpers (proven R7-R9)
// ---------------------------------------------------------------------------
__device__ __forceinline__ void mma_bf16(float* c, const uint32_t* a, const uint32_t* b) {
    asm volatile(
        "mma.sync.aligned.m16n8k16.row.col.f32.bf16.bf16.f32 "
        "{%0,%1,%2,%3}, {%4,%5,%6,%7}, {%8,%9}, {%0,%1,%2,%3};"
        : "+f"(c[0]), "+f"(c[1]), "+f"(c[2]), "+f"(c[3])
        : "r"(a[0]), "r"(a[1]), "r"(a[2]), "r"(a[3]), "r"(b[0]), "r"(b[1]));
}
__device__ __forceinline__ uint32_t pack_bf2(__nv_bfloat16 a, __nv_bfloat16 b) {
    uint16_t ua = *(uint16_t*)&a, ub = *(uint16_t*)&b;
    return (uint32_t)ua | ((uint32_t)ub << 16);   // element0 (lower k) in low bits
}
__device__ __forceinline__ void split2(float x, float y, uint32_t& hi, uint32_t& lo) {
    __nv_bfloat16 hx = __float2bfloat16(x);
    __nv_bfloat16 hy = __float2bfloat16(y);
    __nv_bfloat16 lx = __float2bfloat16(x - __bfloat162float(hx));
    __nv_bfloat16 ly = __float2bfloat16(y - __bfloat162float(hy));
    hi = pack_bf2(hx, hy);
    lo = pack_bf2(lx, ly);
}

// ---------------------------------------------------------------------------
// T5 relative-position bias table (proven)
// ---------------------------------------------------------------------------
__global__ void bias_kernel(const float* __restrict__ rel_emb) {
    int idx = blockIdx.x * 256 + threadIdx.x;
    if (idx >= NH * 4096) return;
    int h = idx >> 12;
    int r = idx & 4095;
    int rel = r - 2047;
    int n0 = -rel;
    int ret = (n0 < 0) ? 16 : 0;
    int nn = (n0 < 0) ? -n0 : n0;
    int b;
    if (nn < 8) {
        b = nn;
    } else {
        float v = logf((float)nn / 8.0f) / (float)2.772588722239781 * 8.0f;
        int vi = 8 + (int)v;
        b = vi < 15 ? vi : 15;
    }
    g_bias[idx] = rel_emb[(ret + b) * NH + h];
}

// ---------------------------------------------------------------------------
// mma.sync split GEMM (proven R9). C[m][n] = A[m][:1024] @ W[:1024][n].
// MODE 0: A=x, W=Wq (N=1024) -> g_q*0.125 | MODE 1: A=x, W=Wkv (N=2048)
// -> g_k/g_v | MODE 2: A=g_ao, W=Wo (N=1024) -> out + bo
// ---------------------------------------------------------------------------
template <int MODE>
__global__ __launch_bounds__(256)
void gemm_mma(const float* __restrict__ A, const float* __restrict__ W,
              float* __restrict__ out, const float* __restrict__ bo) {
    const int N = (MODE == 1) ? 2048 : 1024;
    const int tid = threadIdx.x;
    const int wid = tid >> 5, l = tid & 31;
    const int m0 = blockIdx.y * 128, n0 = blockIdx.x * 128;
    const int wm = wid & 1, wn = wid >> 1;
    const int gId = l >> 2, tig = l & 3;

    const float* Ap = (MODE == 2) ? (const float*)g_ao : A;
    const int rA0 = m0 + wm * 64 + gId;
    const int nB0 = n0 + wn * 32 + gId;

    float C[4][4][4];
#pragma unroll
    for (int a = 0; a < 4; a++)
#pragma unroll
        for (int b = 0; b < 4; b++)
#pragma unroll
            for (int c = 0; c < 4; c++) C[a][b][c] = 0.f;

#pragma unroll 1
    for (int k = 0; k < 1024; k += 16) {
        const int kc = k + 2 * tig;
        uint32_t Ahf[4][4], Alf[4][4];
#pragma unroll
        for (int mf = 0; mf < 4; mf++) {
            const float* Ar0 = Ap + (size_t)(rA0 + mf * 16) * 1024;
            const float* Ar1 = Ar0 + 8 * 1024;
            float2 v00 = *(const float2*)(Ar0 + kc);
            float2 v10 = *(const float2*)(Ar1 + kc);
            float2 v01 = *(const float2*)(Ar0 + kc + 8);
            float2 v11 = *(const float2*)(Ar1 + kc + 8);
            split2(v00.x, v00.y, Ahf[mf][0], Alf[mf][0]);
            split2(v10.x, v10.y, Ahf[mf][1], Alf[mf][1]);
            split2(v01.x, v01.y, Ahf[mf][2], Alf[mf][2]);
            split2(v11.x, v11.y, Ahf[mf][3], Alf[mf][3]);
        }
        uint32_t Bhf[4][2], Blf[4][2];
#pragma unroll
        for (int nf = 0; nf < 4; nf++) {
            int n = nB0 + nf * 8;
            const float* Bc = W + (size_t)kc * N + n;
            float b00 = Bc[0];
            float b01 = Bc[N];
            float b10 = Bc[8 * (size_t)N];
            float b11 = Bc[9 * (size_t)N];
            split2(b00, b01, Bhf[nf][0], Blf[nf][0]);
            split2(b10, b11, Bhf[nf][1], Blf[nf][1]);
        }
#pragma unroll
        for (int mf = 0; mf < 4; mf++)
#pragma unroll
            for (int nf = 0; nf < 4; nf++) {
                mma_bf16(C[mf][nf], Ahf[mf], Bhf[nf]);
                mma_bf16(C[mf][nf], Ahf[mf], Blf[nf]);
                mma_bf16(C[mf][nf], Alf[mf], Bhf[nf]);
            }
    }

#pragma unroll
    for (int mf = 0; mf < 4; mf++) {
#pragma unroll
        for (int half = 0; half < 2; half++) {
            int m = m0 + wm * 64 + mf * 16 + gId + half * 8;
            int bb = m >> 11, ii = m & 2047;
#pragma unroll
            for (int nf = 0; nf < 4; nf++) {
                int c = n0 + wn * 32 + nf * 8 + tig * 2;
                float v0 = C[mf][nf][half * 2], v1 = C[mf][nf][half * 2 + 1];
                if (MODE == 0) {
                    *(float2*)&g_q[((size_t)((bb << 4) + (c >> 6)) * NSEQ + ii) * DH + (c & 63)] =
                        make_float2(v0 * 0.125f, v1 * 0.125f);
                } else if (MODE == 1) {
                    if (c < 1024) {
                        *(float2*)&g_k[((size_t)((bb << 4) + (c >> 6)) * NSEQ + ii) * DH + (c & 63)] =
                            make_float2(v0, v1);
                    } else {
                        int c2 = c - 1024;
                        *(float2*)&g_v[((size_t)((bb << 4) + (c2 >> 6)) * NSEQ + ii) * DH + (c2 & 63)] =
                            make_float2(v0, v1);
                    }
                } else {
                    *(float2*)&out[(size_t)m * DIM + c] =
                        make_float2(v0 + bo[c], v1 + bo[c + 1]);
                }
            }
        }
    }
}

// ---------------------------------------------------------------------------
// Flash attention on mma.sync with inline splits.
// CTA = 128 q-rows x (head, batch). 8 warps; warp w owns rows w*16..w*16+15
// and ALL 64 j-cols per tile -> softmax is intra-warp (quad shfl only).
// S C-fragment is reused directly as the A-fragment of P@V (no smem P).
// Full 4096-entry bias row staged in smem once (no mainloop syncs).
// ---------------------------------------------------------------------------
__global__ __launch_bounds__(256)
void attn_mma_kernel() {
    __shared__ float bias_s[4096];

    const int tid = threadIdx.x;
    const int wid = tid >> 5, l = tid & 31;
    const int gId = l >> 2, tig = l & 3;
    const int i0 = blockIdx.x * 128;
    const int h = blockIdx.y;
    const int bb = blockIdx.z;

    for (int t = tid; t < 4096; t += 256) bias_s[t] = g_bias[h * 4096 + t];

    const size_t base = ((size_t)(bb * NH + h)) * NSEQ * DH;
    const int r0 = i0 + wid * 16 + gId;   // this lane's row (and +8)

    // Q fragments (persist whole loop): k=d, 4 ksteps
    uint32_t Qh[4][4], Ql[4][4];
#pragma unroll
    for (int ks = 0; ks < 4; ks++) {
        const float* q0 = g_q + base + (size_t)r0 * DH + 16 * ks + 2 * tig;
        float2 v00 = *(const float2*)q0;
        float2 v10 = *(const float2*)(q0 + 8 * DH);
        float2 v01 = *(const float2*)(q0 + 8);
        float2 v11 = *(const float2*)(q0 + 8 * DH + 8);
        split2(v00.x, v00.y, Qh[ks][0], Ql[ks][0]);
        split2(v10.x, v10.y, Qh[ks][1], Ql[ks][1]);
        split2(v01.x, v01.y, Qh[ks][2], Ql[ks][2]);
        split2(v11.x, v11.y, Qh[ks][3], Ql[ks][3]);
    }
    __syncthreads();   // bias staged

    float Co[8][4];
#pragma unroll
    for (int nf = 0; nf < 8; nf++)
#pragma unroll
        for (int e = 0; e < 4; e++) Co[nf][e] = 0.f;
    float m0r = -1e30f, m1r = -1e30f, l0r = 0.f, l1r = 0.f;

#pragma unroll 1
    for (int j0 = 0; j0 < NSEQ; j0 += 64) {
        // ---- S = Q K^T (64 j-cols x 16 rows per warp) ----
        float Cs[8][4];
#pragma unroll
        for (int nf = 0; nf < 8; nf++)
#pragma unroll
            for (int e = 0; e < 4; e++) Cs[nf][e] = 0.f;

#pragma unroll
        for (int ks = 0; ks < 4; ks++) {
            uint32_t Kh[8][2], Kl[8][2];
#pragma unroll
            for (int nf = 0; nf < 8; nf++) {
                const float* kp = g_k + base + (size_t)(j0 + gId + 8 * nf) * DH
                                  + 16 * ks + 2 * tig;
                float2 b0 = *(const float2*)kp;
                float2 b1 = *(const float2*)(kp + 8);
                split2(b0.x, b0.y, Kh[nf][0], Kl[nf][0]);
                split2(b1.x, b1.y, Kh[nf][1], Kl[nf][1]);
            }
#pragma unroll
            for (int nf = 0; nf < 8; nf++) {
                mma_bf16(Cs[nf], Qh[ks], Kh[nf]);
                mma_bf16(Cs[nf], Qh[ks], Kl[nf]);
                mma_bf16(Cs[nf], Ql[ks], Kh[nf]);
            }
        }

        // ---- bias + online softmax (intra-warp) ----
        const int bidx0 = j0 - i0 - wid * 16 - gId + 2047;
        float mx0 = -1e30f, mx1 = -1e30f;
#pragma unroll
        for (int nf = 0; nf < 8; nf++) {
            int cb = bidx0 + 8 * nf + 2 * tig;
            Cs[nf][0] += bias_s[cb];
            Cs[nf][1] += bias_s[cb + 1];
            Cs[nf][2] += bias_s[cb - 8];
            Cs[nf][3] += bias_s[cb - 7];
            mx0 = fmaxf(mx0, fmaxf(Cs[nf][0], Cs[nf][1]));
            mx1 = fmaxf(mx1, fmaxf(Cs[nf][2], Cs[nf][3]));
        }
        mx0 = fmaxf(mx0, __shfl_xor_sync(0xffffffffu, mx0, 1));
        mx0 = fmaxf(mx0, __shfl_xor_sync(0xffffffffu, mx0, 2));
        mx1 = fmaxf(mx1, __shfl_xor_sync(0xffffffffu, mx1, 1));
        mx1 = fmaxf(mx1, __shfl_xor_sync(0xffffffffu, mx1, 2));

        float mn0 = fmaxf(m0r, mx0), mn1 = fmaxf(m1r, mx1);
        float al0 = __expf(m0r - mn0), al1 = __expf(m1r - mn1);
        m0r = mn0; m1r = mn1;

        float s0 = 0.f, s1 = 0.f;
#pragma unroll
        for (int nf = 0; nf < 8; nf++) {
            Cs[nf][0] = __expf(Cs[nf][0] - mn0);
            Cs[nf][1] = __expf(Cs[nf][1] - mn0);
            Cs[nf][2] = __expf(Cs[nf][2] - mn1);
            Cs[nf][3] = __expf(Cs[nf][3] - mn1);
            s0 += Cs[nf][0] + Cs[nf][1];
            s1 += Cs[nf][2] + Cs[nf][3];
        }
        s0 += __shfl_xor_sync(0xffffffffu, s0, 1);
        s0 += __shfl_xor_sync(0xffffffffu, s0, 2);
        s1 += __shfl_xor_sync(0xffffffffu, s1, 1);
        s1 += __shfl_xor_sync(0xffffffffu, s1, 2);
        l0r = l0r * al0 + s0;
        l1r = l1r * al1 + s1;

#pragma unroll
        for (int nf = 0; nf < 8; nf++) {
            Co[nf][0] *= al0; Co[nf][1] *= al0;
            Co[nf][2] *= al1; Co[nf][3] *= al1;
        }

        // ---- O += P V : S C-fragment IS the A-fragment ----
#pragma unroll
        for (int ks = 0; ks < 4; ks++) {
            uint32_t Ph[4], Pl[4];
            split2(Cs[2 * ks][0],     Cs[2 * ks][1],     Ph[0], Pl[0]);
            split2(Cs[2 * ks][2],     Cs[2 * ks][3],     Ph[1], Pl[1]);
            split2(Cs[2 * ks + 1][0], Cs[2 * ks + 1][1], Ph[2], Pl[2]);
            split2(Cs[2 * ks + 1][2], Cs[2 * ks + 1][3], Ph[3], Pl[3]);
#pragma unroll
            for (int nf = 0; nf < 8; nf++) {
                const float* vp = g_v + base + (size_t)(j0 + 16 * ks + 2 * tig) * DH
                                  + 8 * nf + gId;
                float v00 = vp[0];
                float v01 = vp[DH];
                float v10 = vp[8 * DH];
                float v11 = vp[9 * DH];
                uint32_t Vh[2], Vl[2];
                split2(v00, v01, Vh[0], Vl[0]);
                split2(v10, v11, Vh[1], Vl[1]);
                mma_bf16(Co[nf], Ph, Vh);
                mma_bf16(Co[nf], Ph, Vl);
                mma_bf16(Co[nf], Pl, Vh);
            }
        }
    }

    // ---- epilogue: normalize, write fp32 g_ao (b, n, h*d) ----
    float inv0 = 1.0f / l0r, inv1 = 1.0f / l1r;
#pragma unroll
    for (int nf = 0; nf < 8; nf++) {
        int c = h * DH + 8 * nf + 2 * tig;
        size_t o0 = ((size_t)(bb * NSEQ + r0)) * DIM + c;
        size_t o1 = ((size_t)(bb * NSEQ + r0 + 8)) * DIM + c;
        *(float2*)&g_ao[o0] = make_float2(Co[nf][0] * inv0, Co[nf][1] * inv0);
        *(float2*)&g_ao[o1] = make_float2(Co[nf][2] * inv1, Co[nf][3] * inv1);
    }
}

// ---------------------------------------------------------------------------
// Launch
// ---------------------------------------------------------------------------
extern "C" void kernel_launch(void* const* d_in, const int* in_sizes, int n_in,
                              void* d_out, int out_size) {
    const float* x       = (const float*)d_in[0];
    const float* Wq      = (const float*)d_in[1];
    const float* Wkv     = (const float*)d_in[2];
    const float* Wo      = (const float*)d_in[3];
    const float* bo      = (const float*)d_in[4];
    const float* rel_emb = (const float*)d_in[5];
    float* out = (float*)d_out;

    bias_kernel<<<(NH * 4096 + 255) / 256, 256>>>(rel_emb);

    dim3 blk(256);
    gemm_mma<0><<<dim3(8, 32), blk>>>(x, Wq, nullptr, nullptr);
    gemm_mma<1><<<dim3(16, 32), blk>>>(x, Wkv, nullptr, nullptr);

    attn_mma_kernel<<<dim3(NSEQ / 128, NH, NB), blk>>>();

    gemm_mma<2><<<dim3(8, 32), blk>>>(nullptr, Wo, out, bo);
}

// round 12
// speedup vs baseline: 1.0535x; 1.0535x over previous
#include <cuda_runtime.h>
#include <cuda_bf16.h>
#include <math.h>
#include <stdint.h>

#define NSEQ 2048
#define NB 2
#define NH 16
#define DH 64
#define DIM 1024

// Scratch (static __device__ — no cudaMalloc allowed)
__device__ __align__(16) float g_ao[NB * NSEQ * DIM];
__device__ __align__(16) float g_bias[NH * 4096];

// Pre-packed bf16x2 operand arrays (written by projection epilogues)
// qh/ql, kh/kl: per (b,h,token): 32 uint32 (pairs along d)
__device__ __align__(16) uint32_t g_qh[NB * NH * NSEQ * 32];
__device__ __align__(16) uint32_t g_ql[NB * NH * NSEQ * 32];
__device__ __align__(16) uint32_t g_kh[NB * NH * NSEQ * 32];
__device__ __align__(16) uint32_t g_kl[NB * NH * NSEQ * 32];
// V transposed: per (b,h,d): NSEQ bf16 (pairs along j when viewed as uint32)
__device__ __align__(16) __nv_bfloat16 g_vth[NB * NH * DH * NSEQ];
__device__ __align__(16) __nv_bfloat16 g_vtl[NB * NH * DH * NSEQ];

// ---------------------------------------------------------------------------
// mma.sync m16n8k16 bf16 + split helpers (proven R7-R10)
// ---------------------------------------------------------------------------
__device__ __forceinline__ void mma_bf16(float* c, const uint32_t* a, const uint32_t* b) {
    asm volatile(
        "mma.sync.aligned.m16n8k16.row.col.f32.bf16.bf16.f32 "
        "{%0,%1,%2,%3}, {%4,%5,%6,%7}, {%8,%9}, {%0,%1,%2,%3};"
        : "+f"(c[0]), "+f"(c[1]), "+f"(c[2]), "+f"(c[3])
        : "r"(a[0]), "r"(a[1]), "r"(a[2]), "r"(a[3]), "r"(b[0]), "r"(b[1]));
}
__device__ __forceinline__ uint32_t pack_bf2(__nv_bfloat16 a, __nv_bfloat16 b) {
    uint16_t ua = *(uint16_t*)&a, ub = *(uint16_t*)&b;
    return (uint32_t)ua | ((uint32_t)ub << 16);   // element0 (lower k) in low bits
}
__device__ __forceinline__ void split2(float x, float y, uint32_t& hi, uint32_t& lo) {
    __nv_bfloat16 hx = __float2bfloat16(x);
    __nv_bfloat16 hy = __float2bfloat16(y);
    __nv_bfloat16 lx = __float2bfloat16(x - __bfloat162float(hx));
    __nv_bfloat16 ly = __float2bfloat16(y - __bfloat162float(hy));
    hi = pack_bf2(hx, hy);
    lo = pack_bf2(lx, ly);
}
__device__ __forceinline__ void splitb(float x, __nv_bfloat16& h, __nv_bfloat16& l) {
    h = __float2bfloat16(x);
    l = __float2bfloat16(x - __bfloat162float(h));
}

// ---------------------------------------------------------------------------
// T5 relative-position bias table (proven)
// ---------------------------------------------------------------------------
__global__ void bias_kernel(const float* __restrict__ rel_emb) {
    int idx = blockIdx.x * 256 + threadIdx.x;
    if (idx >= NH * 4096) return;
    int h = idx >> 12;
    int r = idx & 4095;
    int rel = r - 2047;
    int n0 = -rel;
    int ret = (n0 < 0) ? 16 : 0;
    int nn = (n0 < 0) ? -n0 : n0;
    int b;
    if (nn < 8) {
        b = nn;
    } else {
        float v = logf((float)nn / 8.0f) / (float)2.772588722239781 * 8.0f;
        int vi = 8 + (int)v;
        b = vi < 15 ? vi : 15;
    }
    g_bias[idx] = rel_emb[(ret + b) * NH + h];
}

// ---------------------------------------------------------------------------
// mma.sync split GEMM (proven R9); epilogues now emit packed bf16 operands.
// MODE 0: A=x, W=Wq (N=1024)  -> g_qh/g_ql (scaled 0.125)
// MODE 1: A=x, W=Wkv (N=2048) -> g_kh/g_kl | g_vth/g_vtl (transposed)
// MODE 2: A=g_ao, W=Wo (N=1024) -> out + bo
// ---------------------------------------------------------------------------
template <int MODE>
__global__ __launch_bounds__(256)
void gemm_mma(const float* __restrict__ A, const float* __restrict__ W,
              float* __restrict__ out, const float* __restrict__ bo) {
    const int N = (MODE == 1) ? 2048 : 1024;
    const int tid = threadIdx.x;
    const int wid = tid >> 5, l = tid & 31;
    const int m0 = blockIdx.y * 128, n0 = blockIdx.x * 128;
    const int wm = wid & 1, wn = wid >> 1;
    const int gId = l >> 2, tig = l & 3;

    const float* Ap = (MODE == 2) ? (const float*)g_ao : A;
    const int rA0 = m0 + wm * 64 + gId;
    const int nB0 = n0 + wn * 32 + gId;

    float C[4][4][4];
#pragma unroll
    for (int a = 0; a < 4; a++)
#pragma unroll
        for (int b = 0; b < 4; b++)
#pragma unroll
            for (int c = 0; c < 4; c++) C[a][b][c] = 0.f;

#pragma unroll 1
    for (int k = 0; k < 1024; k += 16) {
        const int kc = k + 2 * tig;
        uint32_t Ahf[4][4], Alf[4][4];
#pragma unroll
        for (int mf = 0; mf < 4; mf++) {
            const float* Ar0 = Ap + (size_t)(rA0 + mf * 16) * 1024;
            const float* Ar1 = Ar0 + 8 * 1024;
            float2 v00 = *(const float2*)(Ar0 + kc);
            float2 v10 = *(const float2*)(Ar1 + kc);
            float2 v01 = *(const float2*)(Ar0 + kc + 8);
            float2 v11 = *(const float2*)(Ar1 + kc + 8);
            split2(v00.x, v00.y, Ahf[mf][0], Alf[mf][0]);
            split2(v10.x, v10.y, Ahf[mf][1], Alf[mf][1]);
            split2(v01.x, v01.y, Ahf[mf][2], Alf[mf][2]);
            split2(v11.x, v11.y, Ahf[mf][3], Alf[mf][3]);
        }
        uint32_t Bhf[4][2], Blf[4][2];
#pragma unroll
        for (int nf = 0; nf < 4; nf++) {
            int n = nB0 + nf * 8;
            const float* Bc = W + (size_t)kc * N + n;
            float b00 = Bc[0];
            float b01 = Bc[N];
            float b10 = Bc[8 * (size_t)N];
            float b11 = Bc[9 * (size_t)N];
            split2(b00, b01, Bhf[nf][0], Blf[nf][0]);
            split2(b10, b11, Bhf[nf][1], Blf[nf][1]);
        }
#pragma unroll
        for (int mf = 0; mf < 4; mf++)
#pragma unroll
            for (int nf = 0; nf < 4; nf++) {
                mma_bf16(C[mf][nf], Ahf[mf], Bhf[nf]);
                mma_bf16(C[mf][nf], Ahf[mf], Blf[nf]);
                mma_bf16(C[mf][nf], Alf[mf], Bhf[nf]);
            }
    }

#pragma unroll
    for (int mf = 0; mf < 4; mf++) {
#pragma unroll
        for (int half = 0; half < 2; half++) {
            int m = m0 + wm * 64 + mf * 16 + gId + half * 8;
            int bb = m >> 11, ii = m & 2047;
#pragma unroll
            for (int nf = 0; nf < 4; nf++) {
                int c = n0 + wn * 32 + nf * 8 + tig * 2;   // even
                float v0 = C[mf][nf][half * 2], v1 = C[mf][nf][half * 2 + 1];
                if (MODE == 0) {
                    // packed q pairs along d, scaled
                    uint32_t hp, lp;
                    split2(v0 * 0.125f, v1 * 0.125f, hp, lp);
                    size_t idx = ((size_t)((bb << 4) + (c >> 6)) * NSEQ + ii) * 32
                                 + ((c & 63) >> 1);
                    g_qh[idx] = hp;
                    g_ql[idx] = lp;
                } else if (MODE == 1) {
                    if (c < 1024) {
                        uint32_t hp, lp;
                        split2(v0, v1, hp, lp);
                        size_t idx = ((size_t)((bb << 4) + (c >> 6)) * NSEQ + ii) * 32
                                     + ((c & 63) >> 1);
                        g_kh[idx] = hp;
                        g_kl[idx] = lp;
                    } else {
                        int c2 = c - 1024;
                        int d = c2 & 63, hh = c2 >> 6;
                        size_t vb = ((size_t)((bb << 4) + hh) * DH + d) * NSEQ + ii;
                        __nv_bfloat16 h0, l0_, h1, l1_;
                        splitb(v0, h0, l0_);
                        splitb(v1, h1, l1_);
                        g_vth[vb] = h0;          g_vtl[vb] = l0_;
                        g_vth[vb + NSEQ] = h1;   g_vtl[vb + NSEQ] = l1_;
                    }
                } else {
                    *(float2*)&out[(size_t)m * DIM + c] =
                        make_float2(v0 + bo[c], v1 + bo[c + 1]);
                }
            }
        }
    }
}

// ---------------------------------------------------------------------------
// Flash attention on mma.sync — all operands pre-packed bf16 hi/lo in gmem.
// CTA = 128 q-rows x (head, batch); 8 warps; warp owns 16 rows x all 64 cols
// per tile (intra-warp softmax, quad shfl). Only P is split in-loop.
// ---------------------------------------------------------------------------
__global__ __launch_bounds__(256)
void attn_mma_kernel() {
    __shared__ float bias_s[4096];

    const int tid = threadIdx.x;
    const int wid = tid >> 5, l = tid & 31;
    const int gId = l >> 2, tig = l & 3;
    const int i0 = blockIdx.x * 128;
    const int h = blockIdx.y;
    const int bb = blockIdx.z;

    for (int t = tid; t < 4096; t += 256) bias_s[t] = g_bias[h * 4096 + t];

    const size_t base2 = (size_t)(bb * NH + h) * NSEQ;     // token base (x32 words)
    const size_t vbase = (size_t)(bb * NH + h) * DH;       // d base (x1024 words)
    const uint32_t* vh32 = (const uint32_t*)g_vth;
    const uint32_t* vl32 = (const uint32_t*)g_vtl;
    const int r0 = i0 + wid * 16 + gId;

    // Q fragments (persist): direct packed loads
    uint32_t Qh[4][4], Ql[4][4];
#pragma unroll
    for (int ks = 0; ks < 4; ks++) {
        size_t q = (base2 + r0) * 32 + 8 * ks + tig;
        Qh[ks][0] = g_qh[q];
        Qh[ks][1] = g_qh[q + 8 * 32];
        Qh[ks][2] = g_qh[q + 4];
        Qh[ks][3] = g_qh[q + 8 * 32 + 4];
        Ql[ks][0] = g_ql[q];
        Ql[ks][1] = g_ql[q + 8 * 32];
        Ql[ks][2] = g_ql[q + 4];
        Ql[ks][3] = g_ql[q + 8 * 32 + 4];
    }
    __syncthreads();   // bias staged

    float Co[8][4];
#pragma unroll
    for (int nf = 0; nf < 8; nf++)
#pragma unroll
        for (int e = 0; e < 4; e++) Co[nf][e] = 0.f;
    float m0r = -1e30f, m1r = -1e30f, l0r = 0.f, l1r = 0.f;

#pragma unroll 1
    for (int j0 = 0; j0 < NSEQ; j0 += 64) {
        // ---- S = Q K^T ----
        float Cs[8][4];
#pragma unroll
        for (int nf = 0; nf < 8; nf++)
#pragma unroll
            for (int e = 0; e < 4; e++) Cs[nf][e] = 0.f;

#pragma unroll
        for (int ks = 0; ks < 4; ks++) {
#pragma unroll
            for (int nf = 0; nf < 8; nf++) {
                size_t kx = (base2 + j0 + gId + 8 * nf) * 32 + 8 * ks + tig;
                uint32_t Kh[2] = {g_kh[kx], g_kh[kx + 4]};
                uint32_t Kl[2] = {g_kl[kx], g_kl[kx + 4]};
                mma_bf16(Cs[nf], Qh[ks], Kh);
                mma_bf16(Cs[nf], Qh[ks], Kl);
                mma_bf16(Cs[nf], Ql[ks], Kh);
            }
        }

        // ---- bias + online softmax (intra-warp) ----
        const int bidx0 = j0 - i0 - wid * 16 - gId + 2047;
        float mx0 = -1e30f, mx1 = -1e30f;
#pragma unroll
        for (int nf = 0; nf < 8; nf++) {
            int cb = bidx0 + 8 * nf + 2 * tig;
            Cs[nf][0] += bias_s[cb];
            Cs[nf][1] += bias_s[cb + 1];
            Cs[nf][2] += bias_s[cb - 8];
            Cs[nf][3] += bias_s[cb - 7];
            mx0 = fmaxf(mx0, fmaxf(Cs[nf][0], Cs[nf][1]));
            mx1 = fmaxf(mx1, fmaxf(Cs[nf][2], Cs[nf][3]));
        }
        mx0 = fmaxf(mx0, __shfl_xor_sync(0xffffffffu, mx0, 1));
        mx0 = fmaxf(mx0, __shfl_xor_sync(0xffffffffu, mx0, 2));
        mx1 = fmaxf(mx1, __shfl_xor_sync(0xffffffffu, mx1, 1));
        mx1 = fmaxf(mx1, __shfl_xor_sync(0xffffffffu, mx1, 2));

        float mn0 = fmaxf(m0r, mx0), mn1 = fmaxf(m1r, mx1);
        float al0 = __expf(m0r - mn0), al1 = __expf(m1r - mn1);
        m0r = mn0; m1r = mn1;

        float s0 = 0.f, s1 = 0.f;
#pragma unroll
        for (int nf = 0; nf < 8; nf++) {
            Cs[nf][0] = __expf(Cs[nf][0] - mn0);
            Cs[nf][1] = __expf(Cs[nf][1] - mn0);
            Cs[nf][2] = __expf(Cs[nf][2] - mn1);
            Cs[nf][3] = __expf(Cs[nf][3] - mn1);
            s0 += Cs[nf][0] + Cs[nf][1];
            s1 += Cs[nf][2] + Cs[nf][3];
        }
        s0 += __shfl_xor_sync(0xffffffffu, s0, 1);
        s0 += __shfl_xor_sync(0xffffffffu, s0, 2);
        s1 += __shfl_xor_sync(0xffffffffu, s1, 1);
        s1 += __shfl_xor_sync(0xffffffffu, s1, 2);
        l0r = l0r * al0 + s0;
        l1r = l1r * al1 + s1;

#pragma unroll
        for (int nf = 0; nf < 8; nf++) {
            Co[nf][0] *= al0; Co[nf][1] *= al0;
            Co[nf][2] *= al1; Co[nf][3] *= al1;
        }

        // ---- O += P V : S C-fragment IS the A-fragment; V pre-transposed ----
#pragma unroll
        for (int ks = 0; ks < 4; ks++) {
            uint32_t Ph[4], Pl[4];
            split2(Cs[2 * ks][0],     Cs[2 * ks][1],     Ph[0], Pl[0]);
            split2(Cs[2 * ks][2],     Cs[2 * ks][3],     Ph[1], Pl[1]);
            split2(Cs[2 * ks + 1][0], Cs[2 * ks + 1][1], Ph[2], Pl[2]);
            split2(Cs[2 * ks + 1][2], Cs[2 * ks + 1][3], Ph[3], Pl[3]);
#pragma unroll
            for (int nf = 0; nf < 8; nf++) {
                size_t vx = (vbase + gId + 8 * nf) * 1024 + (j0 >> 1) + 8 * ks + tig;
                uint32_t Vh[2] = {vh32[vx], vh32[vx + 4]};
                uint32_t Vl[2] = {vl32[vx], vl32[vx + 4]};
                mma_bf16(Co[nf], Ph, Vh);
                mma_bf16(Co[nf], Ph, Vl);
                mma_bf16(Co[nf], Pl, Vh);
            }
        }
    }

    // ---- epilogue: normalize, write fp32 g_ao (b, n, h*d) ----
    float inv0 = 1.0f / l0r, inv1 = 1.0f / l1r;
#pragma unroll
    for (int nf = 0; nf < 8; nf++) {
        int c = h * DH + 8 * nf + 2 * tig;
        size_t o0 = ((size_t)(bb * NSEQ + r0)) * DIM + c;
        size_t o1 = ((size_t)(bb * NSEQ + r0 + 8)) * DIM + c;
        *(float2*)&g_ao[o0] = make_float2(Co[nf][0] * inv0, Co[nf][1] * inv0);
        *(float2*)&g_ao[o1] = make_float2(Co[nf][2] * inv1, Co[nf][3] * inv1);
    }
}

// ---------------------------------------------------------------------------
// Launch
// ---------------------------------------------------------------------------
extern "C" void kernel_launch(void* const* d_in, const int* in_sizes, int n_in,
                              void* d_out, int out_size) {
    const float* x       = (const float*)d_in[0];
    const float* Wq      = (const float*)d_in[1];
    const float* Wkv     = (const float*)d_in[2];
    const float* Wo      = (const float*)d_in[3];
    const float* bo      = (const float*)d_in[4];
    const float* rel_emb = (const float*)d_in[5];
    float* out = (float*)d_out;

    bias_kernel<<<(NH * 4096 + 255) / 256, 256>>>(rel_emb);

    dim3 blk(256);
    gemm_mma<0><<<dim3(8, 32), blk>>>(x, Wq, nullptr, nullptr);
    gemm_mma<1><<<dim3(16, 32), blk>>>(x, Wkv, nullptr, nullptr);

    attn_mma_kernel<<<dim3(NSEQ / 128, NH, NB), blk>>>();

    gemm_mma<2><<<dim3(8, 32), blk>>>(nullptr, Wo, out, bo);
}

// round 16
// speedup vs baseline: 1.8058x; 1.7141x over previous
#include <cuda_runtime.h>
#include <cuda_bf16.h>
#include <math.h>
#include <stdint.h>

#define NSEQ 2048
#define NB 2
#define NH 16
#define DH 64
#define DIM 1024

// Scratch (static __device__ — no cudaMalloc allowed)
__device__ __align__(16) float g_ao[NB * NSEQ * DIM];
__device__ __align__(16) float g_bias[NH * 4096];

// Pre-packed bf16x2 operand arrays (written by projection epilogues)
__device__ __align__(16) uint32_t g_qh[NB * NH * NSEQ * 32];
__device__ __align__(16) uint32_t g_ql[NB * NH * NSEQ * 32];
__device__ __align__(16) uint32_t g_kh[NB * NH * NSEQ * 32];
__device__ __align__(16) uint32_t g_kl[NB * NH * NSEQ * 32];
// V transposed: per (b,h,d): NSEQ bf16 (pairs along j when viewed as uint32)
__device__ __align__(16) __nv_bfloat16 g_vth[NB * NH * DH * NSEQ];
__device__ __align__(16) __nv_bfloat16 g_vtl[NB * NH * DH * NSEQ];

// ---------------------------------------------------------------------------
// mma.sync m16n8k16 bf16 + split helpers (proven R7-R12)
// ---------------------------------------------------------------------------
__device__ __forceinline__ void mma_bf16(float* c, const uint32_t* a, const uint32_t* b) {
    asm volatile(
        "mma.sync.aligned.m16n8k16.row.col.f32.bf16.bf16.f32 "
        "{%0,%1,%2,%3}, {%4,%5,%6,%7}, {%8,%9}, {%0,%1,%2,%3};"
        : "+f"(c[0]), "+f"(c[1]), "+f"(c[2]), "+f"(c[3])
        : "r"(a[0]), "r"(a[1]), "r"(a[2]), "r"(a[3]), "r"(b[0]), "r"(b[1]));
}
__device__ __forceinline__ uint32_t pack_bf2(__nv_bfloat16 a, __nv_bfloat16 b) {
    uint16_t ua = *(uint16_t*)&a, ub = *(uint16_t*)&b;
    return (uint32_t)ua | ((uint32_t)ub << 16);
}
__device__ __forceinline__ void split2(float x, float y, uint32_t& hi, uint32_t& lo) {
    __nv_bfloat16 hx = __float2bfloat16(x);
    __nv_bfloat16 hy = __float2bfloat16(y);
    __nv_bfloat16 lx = __float2bfloat16(x - __bfloat162float(hx));
    __nv_bfloat16 ly = __float2bfloat16(y - __bfloat162float(hy));
    hi = pack_bf2(hx, hy);
    lo = pack_bf2(lx, ly);
}
__device__ __forceinline__ void splitb(float x, __nv_bfloat16& h, __nv_bfloat16& l) {
    h = __float2bfloat16(x);
    l = __float2bfloat16(x - __bfloat162float(h));
}

// ---------------------------------------------------------------------------
// T5 relative-position bias table (proven)
// ---------------------------------------------------------------------------
__global__ void bias_kernel(const float* __restrict__ rel_emb) {
    int idx = blockIdx.x * 256 + threadIdx.x;
    if (idx >= NH * 4096) return;
    int h = idx >> 12;
    int r = idx & 4095;
    int rel = r - 2047;
    int n0 = -rel;
    int ret = (n0 < 0) ? 16 : 0;
    int nn = (n0 < 0) ? -n0 : n0;
    int b;
    if (nn < 8) {
        b = nn;
    } else {
        float v = logf((float)nn / 8.0f) / (float)2.772588722239781 * 8.0f;
        int vi = 8 + (int)v;
        b = vi < 15 ? vi : 15;
    }
    g_bias[idx] = rel_emb[(ret + b) * NH + h];
}

// ---------------------------------------------------------------------------
// mma.sync split GEMM (proven R9/R11); epilogues emit packed bf16 operands.
// MODE 0: A=x, W=Wq (N=1024)  -> g_qh/g_ql (scaled 0.125)
// MODE 1: A=x, W=Wkv (N=2048) -> g_kh/g_kl | g_vth/g_vtl (transposed)
// MODE 2: A=g_ao, W=Wo (N=1024) -> out + bo
// ---------------------------------------------------------------------------
template <int MODE>
__global__ __launch_bounds__(256)
void gemm_mma(const float* __restrict__ A, const float* __restrict__ W,
              float* __restrict__ out, const float* __restrict__ bo) {
    const int N = (MODE == 1) ? 2048 : 1024;
    const int tid = threadIdx.x;
    const int wid = tid >> 5, l = tid & 31;
    const int m0 = blockIdx.y * 128, n0 = blockIdx.x * 128;
    const int wm = wid & 1, wn = wid >> 1;
    const int gId = l >> 2, tig = l & 3;

    const float* Ap = (MODE == 2) ? (const float*)g_ao : A;
    const int rA0 = m0 + wm * 64 + gId;
    const int nB0 = n0 + wn * 32 + gId;

    float C[4][4][4];
#pragma unroll
    for (int a = 0; a < 4; a++)
#pragma unroll
        for (int b = 0; b < 4; b++)
#pragma unroll
            for (int c = 0; c < 4; c++) C[a][b][c] = 0.f;

#pragma unroll 1
    for (int k = 0; k < 1024; k += 16) {
        const int kc = k + 2 * tig;
        uint32_t Ahf[4][4], Alf[4][4];
#pragma unroll
        for (int mf = 0; mf < 4; mf++) {
            const float* Ar0 = Ap + (size_t)(rA0 + mf * 16) * 1024;
            const float* Ar1 = Ar0 + 8 * 1024;
            float2 v00 = *(const float2*)(Ar0 + kc);
            float2 v10 = *(const float2*)(Ar1 + kc);
            float2 v01 = *(const float2*)(Ar0 + kc + 8);
            float2 v11 = *(const float2*)(Ar1 + kc + 8);
            split2(v00.x, v00.y, Ahf[mf][0], Alf[mf][0]);
            split2(v10.x, v10.y, Ahf[mf][1], Alf[mf][1]);
            split2(v01.x, v01.y, Ahf[mf][2], Alf[mf][2]);
            split2(v11.x, v11.y, Ahf[mf][3], Alf[mf][3]);
        }
        uint32_t Bhf[4][2], Blf[4][2];
#pragma unroll
        for (int nf = 0; nf < 4; nf++) {
            int n = nB0 + nf * 8;
            const float* Bc = W + (size_t)kc * N + n;
            float b00 = Bc[0];
            float b01 = Bc[N];
            float b10 = Bc[8 * (size_t)N];
            float b11 = Bc[9 * (size_t)N];
            split2(b00, b01, Bhf[nf][0], Blf[nf][0]);
            split2(b10, b11, Bhf[nf][1], Blf[nf][1]);
        }
#pragma unroll
        for (int mf = 0; mf < 4; mf++)
#pragma unroll
            for (int nf = 0; nf < 4; nf++) {
                mma_bf16(C[mf][nf], Ahf[mf], Bhf[nf]);
                mma_bf16(C[mf][nf], Ahf[mf], Blf[nf]);
                mma_bf16(C[mf][nf], Alf[mf], Bhf[nf]);
            }
    }

#pragma unroll
    for (int mf = 0; mf < 4; mf++) {
#pragma unroll
        for (int half = 0; half < 2; half++) {
            int m = m0 + wm * 64 + mf * 16 + gId + half * 8;
            int bb = m >> 11, ii = m & 2047;
#pragma unroll
            for (int nf = 0; nf < 4; nf++) {
                int c = n0 + wn * 32 + nf * 8 + tig * 2;   // even
                float v0 = C[mf][nf][half * 2], v1 = C[mf][nf][half * 2 + 1];
                if (MODE == 0) {
                    uint32_t hp, lp;
                    split2(v0 * 0.125f, v1 * 0.125f, hp, lp);
                    size_t idx = ((size_t)((bb << 4) + (c >> 6)) * NSEQ + ii) * 32
                                 + ((c & 63) >> 1);
                    g_qh[idx] = hp;
                    g_ql[idx] = lp;
                } else if (MODE == 1) {
                    if (c < 1024) {
                        uint32_t hp, lp;
                        split2(v0, v1, hp, lp);
                        size_t idx = ((size_t)((bb << 4) + (c >> 6)) * NSEQ + ii) * 32
                                     + ((c & 63) >> 1);
                        g_kh[idx] = hp;
                        g_kl[idx] = lp;
                    } else {
                        int c2 = c - 1024;
                        int d = c2 & 63, hh = c2 >> 6;
                        size_t vb = ((size_t)((bb << 4) + hh) * DH + d) * NSEQ + ii;
                        __nv_bfloat16 h0, l0_, h1, l1_;
                        splitb(v0, h0, l0_);
                        splitb(v1, h1, l1_);
                        g_vth[vb] = h0;          g_vtl[vb] = l0_;
                        g_vth[vb + NSEQ] = h1;   g_vtl[vb + NSEQ] = l1_;
                    }
                } else {
                    *(float2*)&out[(size_t)m * DIM + c] =
                        make_float2(v0 + bo[c], v1 + bo[c + 1]);
                }
            }
        }
    }
}

// ---------------------------------------------------------------------------
// Flash attention on mma.sync — K/V tiles staged gmem -> regs -> swizzled smem
// (double-buffered in registers; LDGs for tile t+1 issued before compute of t).
// CTA = 128 q-rows x (head, batch); warp owns 16 rows x all 64 j-cols.
// Swizzle: uint4 (row, a) stored at row*8 + (a ^ (row&7)); fragment loads
// hit banks 4*((2ks)^gId)+tig — a full 32-permutation, conflict-free.
// ---------------------------------------------------------------------------
__global__ __launch_bounds__(256)
void attn_mma_kernel() {
    extern __shared__ char dsm[];
    float* bias_s = (float*)dsm;                       // 16 KB
    uint32_t* sKh = (uint32_t*)(dsm + 16384);          // 8 KB each
    uint32_t* sKl = sKh + 2048;
    uint32_t* sVh = sKl + 2048;
    uint32_t* sVl = sVh + 2048;
    uint4* sKh4 = (uint4*)sKh;
    uint4* sKl4 = (uint4*)sKl;
    uint4* sVh4 = (uint4*)sVh;
    uint4* sVl4 = (uint4*)sVl;

    const int tid = threadIdx.x;
    const int wid = tid >> 5, l = tid & 31;
    const int gId = l >> 2, tig = l & 3;
    const int i0 = blockIdx.x * 128;
    const int h = blockIdx.y;
    const int bb = blockIdx.z;

    for (int t = tid; t < 4096; t += 256) bias_s[t] = g_bias[h * 4096 + t];

    const size_t base2 = (size_t)(bb * NH + h) * NSEQ;
    const size_t vbase = (size_t)(bb * NH + h) * DH;
    const int r0 = i0 + wid * 16 + gId;

    // staging thread mapping: 64 rows x 8 uint4 per array, 2 uint4/thread/array
    const int sr = tid >> 2;          // row 0..63
    const int sa = tid & 3;           // uint4 col (and +4)
    const int sr3 = sr & 7;
    const uint4* Kh4 = (const uint4*)g_kh;
    const uint4* Kl4 = (const uint4*)g_kl;
    const uint4* Vh4 = (const uint4*)g_vth;
    const uint4* Vl4 = (const uint4*)g_vtl;

    // Q fragments (persist whole loop)
    uint32_t Qh[4][4], Ql[4][4];
#pragma unroll
    for (int ks = 0; ks < 4; ks++) {
        size_t q = (base2 + r0) * 32 + 8 * ks + tig;
        Qh[ks][0] = g_qh[q];
        Qh[ks][1] = g_qh[q + 8 * 32];
        Qh[ks][2] = g_qh[q + 4];
        Qh[ks][3] = g_qh[q + 8 * 32 + 4];
        Ql[ks][0] = g_ql[q];
        Ql[ks][1] = g_ql[q + 8 * 32];
        Ql[ks][2] = g_ql[q + 4];
        Ql[ks][3] = g_ql[q + 8 * 32 + 4];
    }

    // prologue: stage tile 0 into registers
    uint4 stKh0, stKh1, stKl0, stKl1, stVh0, stVh1, stVl0, stVl1;
    {
        size_t kr = (base2 + sr) * 8;
        stKh0 = Kh4[kr + sa]; stKh1 = Kh4[kr + sa + 4];
        stKl0 = Kl4[kr + sa]; stKl1 = Kl4[kr + sa + 4];
        size_t vr = (vbase + sr) * 256;
        stVh0 = Vh4[vr + sa]; stVh1 = Vh4[vr + sa + 4];
        stVl0 = Vl4[vr + sa]; stVl1 = Vl4[vr + sa + 4];
    }

    float Co[8][4];
#pragma unroll
    for (int nf = 0; nf < 8; nf++)
#pragma unroll
        for (int e = 0; e < 4; e++) Co[nf][e] = 0.f;
    float m0r = -1e30f, m1r = -1e30f, l0r = 0.f, l1r = 0.f;

#pragma unroll 1
    for (int t = 0; t < 32; t++) {
        const int j0 = t * 64;
        __syncthreads();   // previous compute done reading smem (also bias, t=0)
        {
            int p0 = sr * 8 + (sa ^ sr3);
            int p1 = sr * 8 + ((sa + 4) ^ sr3);
            sKh4[p0] = stKh0; sKh4[p1] = stKh1;
            sKl4[p0] = stKl0; sKl4[p1] = stKl1;
            sVh4[p0] = stVh0; sVh4[p1] = stVh1;
            sVl4[p0] = stVl0; sVl4[p1] = stVl1;
        }
        __syncthreads();
        if (t < 31) {   // prefetch next tile into registers (latency hidden)
            size_t kr = (base2 + j0 + 64 + sr) * 8;
            stKh0 = Kh4[kr + sa]; stKh1 = Kh4[kr + sa + 4];
            stKl0 = Kl4[kr + sa]; stKl1 = Kl4[kr + sa + 4];
            size_t vr = (vbase + sr) * 256 + ((j0 + 64) >> 3);
            stVh0 = Vh4[vr + sa]; stVh1 = Vh4[vr + sa + 4];
            stVl0 = Vl4[vr + sa]; stVl1 = Vl4[vr + sa + 4];
        }

        // ---- S = Q K^T from swizzled smem ----
        float Cs[8][4];
#pragma unroll
        for (int nf = 0; nf < 8; nf++)
#pragma unroll
            for (int e = 0; e < 4; e++) Cs[nf][e] = 0.f;

        const int sw = gId << 2;
#pragma unroll
        for (int ks = 0; ks < 4; ks++) {
            const int w0 = 8 * ks + tig;
            const int o0 = w0 ^ sw, o1 = (w0 + 4) ^ sw;
#pragma unroll
            for (int nf = 0; nf < 8; nf++) {
                int wb = (gId + 8 * nf) * 32;
                uint32_t Kh[2] = {sKh[wb + o0], sKh[wb + o1]};
                uint32_t Kl[2] = {sKl[wb + o0], sKl[wb + o1]};
                mma_bf16(Cs[nf], Qh[ks], Kh);
                mma_bf16(Cs[nf], Qh[ks], Kl);
                mma_bf16(Cs[nf], Ql[ks], Kh);
            }
        }

        // ---- bias + online softmax (intra-warp) ----
        const int bidx0 = j0 - i0 - wid * 16 - gId + 2047;
        float mx0 = -1e30f, mx1 = -1e30f;
#pragma unroll
        for (int nf = 0; nf < 8; nf++) {
            int cb = bidx0 + 8 * nf + 2 * tig;
            Cs[nf][0] += bias_s[cb];
            Cs[nf][1] += bias_s[cb + 1];
            Cs[nf][2] += bias_s[cb - 8];
            Cs[nf][3] += bias_s[cb - 7];
            mx0 = fmaxf(mx0, fmaxf(Cs[nf][0], Cs[nf][1]));
            mx1 = fmaxf(mx1, fmaxf(Cs[nf][2], Cs[nf][3]));
        }
        mx0 = fmaxf(mx0, __shfl_xor_sync(0xffffffffu, mx0, 1));
        mx0 = fmaxf(mx0, __shfl_xor_sync(0xffffffffu, mx0, 2));
        mx1 = fmaxf(mx1, __shfl_xor_sync(0xffffffffu, mx1, 1));
        mx1 = fmaxf(mx1, __shfl_xor_sync(0xffffffffu, mx1, 2));

        float mn0 = fmaxf(m0r, mx0), mn1 = fmaxf(m1r, mx1);
        float al0 = __expf(m0r - mn0), al1 = __expf(m1r - mn1);
        m0r = mn0; m1r = mn1;

        float s0 = 0.f, s1 = 0.f;
#pragma unroll
        for (int nf = 0; nf < 8; nf++) {
            Cs[nf][0] = __expf(Cs[nf][0] - mn0);
            Cs[nf][1] = __expf(Cs[nf][1] - mn0);
            Cs[nf][2] = __expf(Cs[nf][2] - mn1);
            Cs[nf][3] = __expf(Cs[nf][3] - mn1);
            s0 += Cs[nf][0] + Cs[nf][1];
            s1 += Cs[nf][2] + Cs[nf][3];
        }
        s0 += __shfl_xor_sync(0xffffffffu, s0, 1);
        s0 += __shfl_xor_sync(0xffffffffu, s0, 2);
        s1 += __shfl_xor_sync(0xffffffffu, s1, 1);
        s1 += __shfl_xor_sync(0xffffffffu, s1, 2);
        l0r = l0r * al0 + s0;
        l1r = l1r * al1 + s1;

#pragma unroll
        for (int nf = 0; nf < 8; nf++) {
            Co[nf][0] *= al0; Co[nf][1] *= al0;
            Co[nf][2] *= al1; Co[nf][3] *= al1;
        }

        // ---- O += P V : S C-fragment IS the A-fragment; V from smem ----
#pragma unroll
        for (int ks = 0; ks < 4; ks++) {
            uint32_t Ph[4], Pl[4];
            split2(Cs[2 * ks][0],     Cs[2 * ks][1],     Ph[0], Pl[0]);
            split2(Cs[2 * ks][2],     Cs[2 * ks][3],     Ph[1], Pl[1]);
            split2(Cs[2 * ks + 1][0], Cs[2 * ks + 1][1], Ph[2], Pl[2]);
            split2(Cs[2 * ks + 1][2], Cs[2 * ks + 1][3], Ph[3], Pl[3]);
            const int w0 = 8 * ks + tig;
            const int o0 = w0 ^ sw, o1 = (w0 + 4) ^ sw;
#pragma unroll
            for (int nf = 0; nf < 8; nf++) {
                int wb = (gId + 8 * nf) * 32;
                uint32_t Vh[2] = {sVh[wb + o0], sVh[wb + o1]};
                uint32_t Vl[2] = {sVl[wb + o0], sVl[wb + o1]};
                mma_bf16(Co[nf], Ph, Vh);
                mma_bf16(Co[nf], Ph, Vl);
                mma_bf16(Co[nf], Pl, Vh);
            }
        }
    }

    // ---- epilogue: normalize, write fp32 g_ao (b, n, h*d) ----
    float inv0 = 1.0f / l0r, inv1 = 1.0f / l1r;
#pragma unroll
    for (int nf = 0; nf < 8; nf++) {
        int c = h * DH + 8 * nf + 2 * tig;
        size_t o0 = ((size_t)(bb * NSEQ + r0)) * DIM + c;
        size_t o1 = ((size_t)(bb * NSEQ + r0 + 8)) * DIM + c;
        *(float2*)&g_ao[o0] = make_float2(Co[nf][0] * inv0, Co[nf][1] * inv0);
        *(float2*)&g_ao[o1] = make_float2(Co[nf][2] * inv1, Co[nf][3] * inv1);
    }
}

// ---------------------------------------------------------------------------
// Launch
// ---------------------------------------------------------------------------
extern "C" void kernel_launch(void* const* d_in, const int* in_sizes, int n_in,
                              void* d_out, int out_size) {
    const float* x       = (const float*)d_in[0];
    const float* Wq      = (const float*)d_in[1];
    const float* Wkv     = (const float*)d_in[2];
    const float* Wo      = (const float*)d_in[3];
    const float* bo      = (const float*)d_in[4];
    const float* rel_emb = (const float*)d_in[5];
    float* out = (float*)d_out;

    bias_kernel<<<(NH * 4096 + 255) / 256, 256>>>(rel_emb);

    dim3 blk(256);
    gemm_mma<0><<<dim3(8, 32), blk>>>(x, Wq, nullptr, nullptr);
    gemm_mma<1><<<dim3(16, 32), blk>>>(x, Wkv, nullptr, nullptr);

    const int asm_bytes = 16384 + 4 * 8192;   // 49,152 B
    cudaFuncSetAttribute(attn_mma_kernel,
                         cudaFuncAttributeMaxDynamicSharedMemorySize, asm_bytes);
    attn_mma_kernel<<<dim3(NSEQ / 128, NH, NB), blk, asm_bytes>>>();

    gemm_mma<2><<<dim3(8, 32), blk>>>(nullptr, Wo, out, bo);
}

// round 17
// speedup vs baseline: 2.0951x; 1.1602x over previous
#include <cuda_runtime.h>
#include <cuda_bf16.h>
#include <math.h>
#include <stdint.h>

#define NSEQ 2048
#define NB 2
#define NH 16
#define DH 64
#define DIM 1024

// Scratch (static __device__ — no cudaMalloc allowed)
__device__ __align__(16) float g_ao[NB * NSEQ * DIM];
__device__ __align__(16) float g_bias[NH * 4096];

// Pre-packed bf16x2 operand arrays (written by projection epilogues)
__device__ __align__(16) uint32_t g_qh[NB * NH * NSEQ * 32];
__device__ __align__(16) uint32_t g_ql[NB * NH * NSEQ * 32];
__device__ __align__(16) uint32_t g_kh[NB * NH * NSEQ * 32];
__device__ __align__(16) uint32_t g_kl[NB * NH * NSEQ * 32];
// V transposed: per (b,h,d): NSEQ bf16 (pairs along j when viewed as uint32)
__device__ __align__(16) __nv_bfloat16 g_vth[NB * NH * DH * NSEQ];
__device__ __align__(16) __nv_bfloat16 g_vtl[NB * NH * DH * NSEQ];

// ---------------------------------------------------------------------------
// mma.sync m16n8k16 bf16 + split helpers (proven R7-R16)
// ---------------------------------------------------------------------------
__device__ __forceinline__ void mma_bf16(float* c, const uint32_t* a, const uint32_t* b) {
    asm volatile(
        "mma.sync.aligned.m16n8k16.row.col.f32.bf16.bf16.f32 "
        "{%0,%1,%2,%3}, {%4,%5,%6,%7}, {%8,%9}, {%0,%1,%2,%3};"
        : "+f"(c[0]), "+f"(c[1]), "+f"(c[2]), "+f"(c[3])
        : "r"(a[0]), "r"(a[1]), "r"(a[2]), "r"(a[3]), "r"(b[0]), "r"(b[1]));
}
__device__ __forceinline__ uint32_t pack_bf2(__nv_bfloat16 a, __nv_bfloat16 b) {
    uint16_t ua = *(uint16_t*)&a, ub = *(uint16_t*)&b;
    return (uint32_t)ua | ((uint32_t)ub << 16);
}
__device__ __forceinline__ void split2(float x, float y, uint32_t& hi, uint32_t& lo) {
    __nv_bfloat16 hx = __float2bfloat16(x);
    __nv_bfloat16 hy = __float2bfloat16(y);
    __nv_bfloat16 lx = __float2bfloat16(x - __bfloat162float(hx));
    __nv_bfloat16 ly = __float2bfloat16(y - __bfloat162float(hy));
    hi = pack_bf2(hx, hy);
    lo = pack_bf2(lx, ly);
}
__device__ __forceinline__ void splitb(float x, __nv_bfloat16& h, __nv_bfloat16& l) {
    h = __float2bfloat16(x);
    l = __float2bfloat16(x - __bfloat162float(h));
}

// ---------------------------------------------------------------------------
// T5 relative-position bias table (proven)
// ---------------------------------------------------------------------------
__global__ void bias_kernel(const float* __restrict__ rel_emb) {
    int idx = blockIdx.x * 256 + threadIdx.x;
    if (idx >= NH * 4096) return;
    int h = idx >> 12;
    int r = idx & 4095;
    int rel = r - 2047;
    int n0 = -rel;
    int ret = (n0 < 0) ? 16 : 0;
    int nn = (n0 < 0) ? -n0 : n0;
    int b;
    if (nn < 8) {
        b = nn;
    } else {
        float v = logf((float)nn / 8.0f) / (float)2.772588722239781 * 8.0f;
        int vi = 8 + (int)v;
        b = vi < 15 ? vi : 15;
    }
    g_bias[idx] = rel_emb[(ret + b) * NH + h];
}

// ---------------------------------------------------------------------------
// mma.sync split GEMM v3 — smem-staged (R16 recipe applied to projections).
// CTA 128x128, 256 thr, 8 warps (2M x 4N of 64x32). K chunks of 64 (4 ksteps).
// Per chunk: reg-prefetched coalesced LDG; A split once -> swizzled packed smem;
// W staged fp32 (132-stride, conflict-free) then transpose-packed to B smem.
// Mainloop: LDS fragments (attention-proven swizzle) + 3-term mma.
// MODE 0: A=x, W=Wq (N=1024)  -> g_qh/g_ql (scaled 0.125)
// MODE 1: A=x, W=Wkv (N=2048) -> g_kh/g_kl | g_vth/g_vtl (transposed)
// MODE 2: A=g_ao, W=Wo (N=1024) -> out + bo
// ---------------------------------------------------------------------------
template <int MODE>
__global__ __launch_bounds__(256)
void gemm_mma(const float* __restrict__ A, const float* __restrict__ W,
              float* __restrict__ out, const float* __restrict__ bo) {
    const int N = (MODE == 1) ? 2048 : 1024;
    extern __shared__ char gsm[];
    uint32_t* sAh = (uint32_t*)gsm;            // [128 rows][32 words] swizzled
    uint32_t* sAl = sAh + 4096;
    uint32_t* sBh = sAl + 4096;                // [128 n-rows][32 kpair words]
    uint32_t* sBl = sBh + 4096;
    float*    sW  = (float*)(sBl + 4096);      // [64 k][132] fp32 staging
    uint4* sAh4 = (uint4*)sAh;
    uint4* sAl4 = (uint4*)sAl;
    uint4* sBh4 = (uint4*)sBh;
    uint4* sBl4 = (uint4*)sBl;

    const int tid = threadIdx.x;
    const int wid = tid >> 5, l = tid & 31;
    const int m0 = blockIdx.y * 128, n0 = blockIdx.x * 128;
    const int wm = wid & 1, wn = wid >> 1;
    const int gId = l >> 2, tig = l & 3;

    const float* Ap = (MODE == 2) ? (const float*)g_ao : A;

    // staging maps
    const int ra = tid >> 1, khalf = tid & 1;   // A: row, k-half (32 floats)
    const int q4 = (tid & 31) * 4;              // W phase1: n offset (4 floats)
    const int kw0 = (tid >> 5) * 8;             // W phase1: 8 k-rows
    const int pn = tid & 127, pah = tid >> 7;   // phase2: n-row, a-half

    float4 Ar[8], Wr[8];
    {
        const float* Arow = Ap + (size_t)(m0 + ra) * 1024 + khalf * 32;
#pragma unroll
        for (int i = 0; i < 8; i++) Ar[i] = *(const float4*)(Arow + 4 * i);
#pragma unroll
        for (int i = 0; i < 8; i++)
            Wr[i] = *(const float4*)(W + (size_t)(kw0 + i) * N + n0 + q4);
    }

    float C[4][4][4];
#pragma unroll
    for (int a = 0; a < 4; a++)
#pragma unroll
        for (int b = 0; b < 4; b++)
#pragma unroll
            for (int c = 0; c < 4; c++) C[a][b][c] = 0.f;

#pragma unroll 1
    for (int ch = 0; ch < 16; ch++) {
        __syncthreads();   // previous compute finished reading sA/sB; sW free
        // A: split in regs -> packed swizzled smem
#pragma unroll
        for (int j = 0; j < 4; j++) {
            uint4 hv, lv;
            split2(Ar[2 * j].x, Ar[2 * j].y, hv.x, lv.x);
            split2(Ar[2 * j].z, Ar[2 * j].w, hv.y, lv.y);
            split2(Ar[2 * j + 1].x, Ar[2 * j + 1].y, hv.z, lv.z);
            split2(Ar[2 * j + 1].z, Ar[2 * j + 1].w, hv.w, lv.w);
            int p = ra * 8 + ((4 * khalf + j) ^ (ra & 7));
            sAh4[p] = hv;
            sAl4[p] = lv;
        }
        // W: raw fp32 stage (conflict-free: warp = one k-row, 128 contiguous n)
#pragma unroll
        for (int i = 0; i < 8; i++)
            *(float4*)(sW + (kw0 + i) * 132 + q4) = Wr[i];
        __syncthreads();
        // phase2: transpose-pack W -> sBh/sBl
#pragma unroll
        for (int j = 0; j < 4; j++) {
            int a = 4 * pah + j;
            uint4 hv, lv;
#pragma unroll
            for (int c = 0; c < 4; c++) {
                int k2 = 2 * (4 * a + c);
                float w0v = sW[k2 * 132 + pn];
                float w1v = sW[(k2 + 1) * 132 + pn];
                uint32_t hh, ll;
                split2(w0v, w1v, hh, ll);
                ((uint32_t*)&hv)[c] = hh;
                ((uint32_t*)&lv)[c] = ll;
            }
            int p = pn * 8 + (a ^ (pn & 7));
            sBh4[p] = hv;
            sBl4[p] = lv;
        }
        // prefetch next chunk (LDGs in flight during compute)
        if (ch < 15) {
            int kc = 64 * (ch + 1);
            const float* Arow = Ap + (size_t)(m0 + ra) * 1024 + kc + khalf * 32;
#pragma unroll
            for (int i = 0; i < 8; i++) Ar[i] = *(const float4*)(Arow + 4 * i);
#pragma unroll
            for (int i = 0; i < 8; i++)
                Wr[i] = *(const float4*)(W + (size_t)(kc + kw0 + i) * N + n0 + q4);
        }
        __syncthreads();

        // compute: 4 ksteps from swizzled smem
        const int sw = gId << 2;
#pragma unroll
        for (int ks = 0; ks < 4; ks++) {
            const int o0 = (8 * ks + tig) ^ sw;
            const int o1 = (8 * ks + tig + 4) ^ sw;
            uint32_t Ahf[4][4], Alf[4][4];
#pragma unroll
            for (int mf = 0; mf < 4; mf++) {
                int r = wm * 64 + mf * 16 + gId;
                Ahf[mf][0] = sAh[r * 32 + o0];
                Ahf[mf][1] = sAh[(r + 8) * 32 + o0];
                Ahf[mf][2] = sAh[r * 32 + o1];
                Ahf[mf][3] = sAh[(r + 8) * 32 + o1];
                Alf[mf][0] = sAl[r * 32 + o0];
                Alf[mf][1] = sAl[(r + 8) * 32 + o0];
                Alf[mf][2] = sAl[r * 32 + o1];
                Alf[mf][3] = sAl[(r + 8) * 32 + o1];
            }
#pragma unroll
            for (int nf = 0; nf < 4; nf++) {
                int nn = wn * 32 + nf * 8 + gId;
                uint32_t Bh_[2] = {sBh[nn * 32 + o0], sBh[nn * 32 + o1]};
                uint32_t Bl_[2] = {sBl[nn * 32 + o0], sBl[nn * 32 + o1]};
#pragma unroll
                for (int mf = 0; mf < 4; mf++) {
                    mma_bf16(C[mf][nf], Ahf[mf], Bh_);
                    mma_bf16(C[mf][nf], Ahf[mf], Bl_);
                    mma_bf16(C[mf][nf], Alf[mf], Bh_);
                }
            }
        }
    }

    // Epilogue (unchanged from proven R11 version)
#pragma unroll
    for (int mf = 0; mf < 4; mf++) {
#pragma unroll
        for (int half = 0; half < 2; half++) {
            int m = m0 + wm * 64 + mf * 16 + gId + half * 8;
            int bb = m >> 11, ii = m & 2047;
#pragma unroll
            for (int nf = 0; nf < 4; nf++) {
                int c = n0 + wn * 32 + nf * 8 + tig * 2;   // even
                float v0 = C[mf][nf][half * 2], v1 = C[mf][nf][half * 2 + 1];
                if (MODE == 0) {
                    uint32_t hp, lp;
                    split2(v0 * 0.125f, v1 * 0.125f, hp, lp);
                    size_t idx = ((size_t)((bb << 4) + (c >> 6)) * NSEQ + ii) * 32
                                 + ((c & 63) >> 1);
                    g_qh[idx] = hp;
                    g_ql[idx] = lp;
                } else if (MODE == 1) {
                    if (c < 1024) {
                        uint32_t hp, lp;
                        split2(v0, v1, hp, lp);
                        size_t idx = ((size_t)((bb << 4) + (c >> 6)) * NSEQ + ii) * 32
                                     + ((c & 63) >> 1);
                        g_kh[idx] = hp;
                        g_kl[idx] = lp;
                    } else {
                        int c2 = c - 1024;
                        int d = c2 & 63, hh = c2 >> 6;
                        size_t vb = ((size_t)((bb << 4) + hh) * DH + d) * NSEQ + ii;
                        __nv_bfloat16 h0, l0_, h1, l1_;
                        splitb(v0, h0, l0_);
                        splitb(v1, h1, l1_);
                        g_vth[vb] = h0;          g_vtl[vb] = l0_;
                        g_vth[vb + NSEQ] = h1;   g_vtl[vb + NSEQ] = l1_;
                    }
                } else {
                    *(float2*)&out[(size_t)m * DIM + c] =
                        make_float2(v0 + bo[c], v1 + bo[c + 1]);
                }
            }
        }
    }
}

// ---------------------------------------------------------------------------
// Flash attention on mma.sync — unchanged from R16 (proven, 403 us)
// ---------------------------------------------------------------------------
__global__ __launch_bounds__(256)
void attn_mma_kernel() {
    extern __shared__ char dsm[];
    float* bias_s = (float*)dsm;                       // 16 KB
    uint32_t* sKh = (uint32_t*)(dsm + 16384);          // 8 KB each
    uint32_t* sKl = sKh + 2048;
    uint32_t* sVh = sKl + 2048;
    uint32_t* sVl = sVh + 2048;
    uint4* sKh4 = (uint4*)sKh;
    uint4* sKl4 = (uint4*)sKl;
    uint4* sVh4 = (uint4*)sVh;
    uint4* sVl4 = (uint4*)sVl;

    const int tid = threadIdx.x;
    const int wid = tid >> 5, l = tid & 31;
    const int gId = l >> 2, tig = l & 3;
    const int i0 = blockIdx.x * 128;
    const int h = blockIdx.y;
    const int bb = blockIdx.z;

    for (int t = tid; t < 4096; t += 256) bias_s[t] = g_bias[h * 4096 + t];

    const size_t base2 = (size_t)(bb * NH + h) * NSEQ;
    const size_t vbase = (size_t)(bb * NH + h) * DH;
    const int r0 = i0 + wid * 16 + gId;

    const int sr = tid >> 2;
    const int sa = tid & 3;
    const int sr3 = sr & 7;
    const uint4* Kh4 = (const uint4*)g_kh;
    const uint4* Kl4 = (const uint4*)g_kl;
    const uint4* Vh4 = (const uint4*)g_vth;
    const uint4* Vl4 = (const uint4*)g_vtl;

    uint32_t Qh[4][4], Ql[4][4];
#pragma unroll
    for (int ks = 0; ks < 4; ks++) {
        size_t q = (base2 + r0) * 32 + 8 * ks + tig;
        Qh[ks][0] = g_qh[q];
        Qh[ks][1] = g_qh[q + 8 * 32];
        Qh[ks][2] = g_qh[q + 4];
        Qh[ks][3] = g_qh[q + 8 * 32 + 4];
        Ql[ks][0] = g_ql[q];
        Ql[ks][1] = g_ql[q + 8 * 32];
        Ql[ks][2] = g_ql[q + 4];
        Ql[ks][3] = g_ql[q + 8 * 32 + 4];
    }

    uint4 stKh0, stKh1, stKl0, stKl1, stVh0, stVh1, stVl0, stVl1;
    {
        size_t kr = (base2 + sr) * 8;
        stKh0 = Kh4[kr + sa]; stKh1 = Kh4[kr + sa + 4];
        stKl0 = Kl4[kr + sa]; stKl1 = Kl4[kr + sa + 4];
        size_t vr = (vbase + sr) * 256;
        stVh0 = Vh4[vr + sa]; stVh1 = Vh4[vr + sa + 4];
        stVl0 = Vl4[vr + sa]; stVl1 = Vl4[vr + sa + 4];
    }

    float Co[8][4];
#pragma unroll
    for (int nf = 0; nf < 8; nf++)
#pragma unroll
        for (int e = 0; e < 4; e++) Co[nf][e] = 0.f;
    float m0r = -1e30f, m1r = -1e30f, l0r = 0.f, l1r = 0.f;

#pragma unroll 1
    for (int t = 0; t < 32; t++) {
        const int j0 = t * 64;
        __syncthreads();
        {
            int p0 = sr * 8 + (sa ^ sr3);
            int p1 = sr * 8 + ((sa + 4) ^ sr3);
            sKh4[p0] = stKh0; sKh4[p1] = stKh1;
            sKl4[p0] = stKl0; sKl4[p1] = stKl1;
            sVh4[p0] = stVh0; sVh4[p1] = stVh1;
            sVl4[p0] = stVl0; sVl4[p1] = stVl1;
        }
        __syncthreads();
        if (t < 31) {
            size_t kr = (base2 + j0 + 64 + sr) * 8;
            stKh0 = Kh4[kr + sa]; stKh1 = Kh4[kr + sa + 4];
            stKl0 = Kl4[kr + sa]; stKl1 = Kl4[kr + sa + 4];
            size_t vr = (vbase + sr) * 256 + ((j0 + 64) >> 3);
            stVh0 = Vh4[vr + sa]; stVh1 = Vh4[vr + sa + 4];
            stVl0 = Vl4[vr + sa]; stVl1 = Vl4[vr + sa + 4];
        }

        float Cs[8][4];
#pragma unroll
        for (int nf = 0; nf < 8; nf++)
#pragma unroll
            for (int e = 0; e < 4; e++) Cs[nf][e] = 0.f;

        const int sw = gId << 2;
#pragma unroll
        for (int ks = 0; ks < 4; ks++) {
            const int w0 = 8 * ks + tig;
            const int o0 = w0 ^ sw, o1 = (w0 + 4) ^ sw;
#pragma unroll
            for (int nf = 0; nf < 8; nf++) {
                int wb = (gId + 8 * nf) * 32;
                uint32_t Kh[2] = {sKh[wb + o0], sKh[wb + o1]};
                uint32_t Kl[2] = {sKl[wb + o0], sKl[wb + o1]};
                mma_bf16(Cs[nf], Qh[ks], Kh);
                mma_bf16(Cs[nf], Qh[ks], Kl);
                mma_bf16(Cs[nf], Ql[ks], Kh);
            }
        }

        const int bidx0 = j0 - i0 - wid * 16 - gId + 2047;
        float mx0 = -1e30f, mx1 = -1e30f;
#pragma unroll
        for (int nf = 0; nf < 8; nf++) {
            int cb = bidx0 + 8 * nf + 2 * tig;
            Cs[nf][0] += bias_s[cb];
            Cs[nf][1] += bias_s[cb + 1];
            Cs[nf][2] += bias_s[cb - 8];
            Cs[nf][3] += bias_s[cb - 7];
            mx0 = fmaxf(mx0, fmaxf(Cs[nf][0], Cs[nf][1]));
            mx1 = fmaxf(mx1, fmaxf(Cs[nf][2], Cs[nf][3]));
        }
        mx0 = fmaxf(mx0, __shfl_xor_sync(0xffffffffu, mx0, 1));
        mx0 = fmaxf(mx0, __shfl_xor_sync(0xffffffffu, mx0, 2));
        mx1 = fmaxf(mx1, __shfl_xor_sync(0xffffffffu, mx1, 1));
        mx1 = fmaxf(mx1, __shfl_xor_sync(0xffffffffu, mx1, 2));

        float mn0 = fmaxf(m0r, mx0), mn1 = fmaxf(m1r, mx1);
        float al0 = __expf(m0r - mn0), al1 = __expf(m1r - mn1);
        m0r = mn0; m1r = mn1;

        float s0 = 0.f, s1 = 0.f;
#pragma unroll
        for (int nf = 0; nf < 8; nf++) {
            Cs[nf][0] = __expf(Cs[nf][0] - mn0);
            Cs[nf][1] = __expf(Cs[nf][1] - mn0);
            Cs[nf][2] = __expf(Cs[nf][2] - mn1);
            Cs[nf][3] = __expf(Cs[nf][3] - mn1);
            s0 += Cs[nf][0] + Cs[nf][1];
            s1 += Cs[nf][2] + Cs[nf][3];
        }
        s0 += __shfl_xor_sync(0xffffffffu, s0, 1);
        s0 += __shfl_xor_sync(0xffffffffu, s0, 2);
        s1 += __shfl_xor_sync(0xffffffffu, s1, 1);
        s1 += __shfl_xor_sync(0xffffffffu, s1, 2);
        l0r = l0r * al0 + s0;
        l1r = l1r * al1 + s1;

#pragma unroll
        for (int nf = 0; nf < 8; nf++) {
            Co[nf][0] *= al0; Co[nf][1] *= al0;
            Co[nf][2] *= al1; Co[nf][3] *= al1;
        }

#pragma unroll
        for (int ks = 0; ks < 4; ks++) {
            uint32_t Ph[4], Pl[4];
            split2(Cs[2 * ks][0],     Cs[2 * ks][1],     Ph[0], Pl[0]);
            split2(Cs[2 * ks][2],     Cs[2 * ks][3],     Ph[1], Pl[1]);
            split2(Cs[2 * ks + 1][0], Cs[2 * ks + 1][1], Ph[2], Pl[2]);
            split2(Cs[2 * ks + 1][2], Cs[2 * ks + 1][3], Ph[3], Pl[3]);
            const int w0 = 8 * ks + tig;
            const int o0 = w0 ^ sw, o1 = (w0 + 4) ^ sw;
#pragma unroll
            for (int nf = 0; nf < 8; nf++) {
                int wb = (gId + 8 * nf) * 32;
                uint32_t Vh[2] = {sVh[wb + o0], sVh[wb + o1]};
                uint32_t Vl[2] = {sVl[wb + o0], sVl[wb + o1]};
                mma_bf16(Co[nf], Ph, Vh);
                mma_bf16(Co[nf], Ph, Vl);
                mma_bf16(Co[nf], Pl, Vh);
            }
        }
    }

    float inv0 = 1.0f / l0r, inv1 = 1.0f / l1r;
#pragma unroll
    for (int nf = 0; nf < 8; nf++) {
        int c = h * DH + 8 * nf + 2 * tig;
        size_t o0 = ((size_t)(bb * NSEQ + r0)) * DIM + c;
        size_t o1 = ((size_t)(bb * NSEQ + r0 + 8)) * DIM + c;
        *(float2*)&g_ao[o0] = make_float2(Co[nf][0] * inv0, Co[nf][1] * inv0);
        *(float2*)&g_ao[o1] = make_float2(Co[nf][2] * inv1, Co[nf][3] * inv1);
    }
}

// ---------------------------------------------------------------------------
// Launch
// ---------------------------------------------------------------------------
extern "C" void kernel_launch(void* const* d_in, const int* in_sizes, int n_in,
                              void* d_out, int out_size) {
    const float* x       = (const float*)d_in[0];
    const float* Wq      = (const float*)d_in[1];
    const float* Wkv     = (const float*)d_in[2];
    const float* Wo      = (const float*)d_in[3];
    const float* bo      = (const float*)d_in[4];
    const float* rel_emb = (const float*)d_in[5];
    float* out = (float*)d_out;

    bias_kernel<<<(NH * 4096 + 255) / 256, 256>>>(rel_emb);

    dim3 blk(256);
    const int gsm_bytes = 4 * 16384 + 64 * 132 * 4;   // 99,328 B
    cudaFuncSetAttribute(gemm_mma<0>, cudaFuncAttributeMaxDynamicSharedMemorySize,
                         gsm_bytes);
    cudaFuncSetAttribute(gemm_mma<1>, cudaFuncAttributeMaxDynamicSharedMemorySize,
                         gsm_bytes);
    cudaFuncSetAttribute(gemm_mma<2>, cudaFuncAttributeMaxDynamicSharedMemorySize,
                         gsm_bytes);

    gemm_mma<0><<<dim3(8, 32), blk, gsm_bytes>>>(x, Wq, nullptr, nullptr);
    gemm_mma<1><<<dim3(16, 32), blk, gsm_bytes>>>(x, Wkv, nullptr, nullptr);

    const int asm_bytes = 16384 + 4 * 8192;   // 49,152 B
    cudaFuncSetAttribute(attn_mma_kernel,
                         cudaFuncAttributeMaxDynamicSharedMemorySize, asm_bytes);
    attn_mma_kernel<<<dim3(NSEQ / 128, NH, NB), blk, asm_bytes>>>();

    gemm_mma<2><<<dim3(8, 32), blk, gsm_bytes>>>(nullptr, Wo, out, bo);
}